// round 2
// baseline (speedup 1.0000x reference)
#include <cuda_runtime.h>

#define NH    12
#define DK    64
#define DM    768
#define BATCH 2
#define SEQ   4096
#define MTOT  (BATCH*SEQ)   // 8192

// Scratch (device globals: allocation-free rule)
__device__ float g_q[BATCH*NH*SEQ*DK];
__device__ float g_k[BATCH*NH*SEQ*DK];
__device__ float g_v[BATCH*NH*SEQ*DK];
__device__ float g_o[MTOT*DM];

// ---------------------------------------------------------------------------
// NT GEMM: C[M,N] = A[M,K] * B[N,K]^T + bias[N]
// M=8192, N=768, K=768. 64x64 tile, 16-wide K slab, 256 threads, 4x4/thread.
// split=1: write out[b,h,s,d] split-heads layout; split=0: row-major [M,N].
// ---------------------------------------------------------------------------
__global__ __launch_bounds__(256) void proj_nt(
    const float* __restrict__ X, const float* __restrict__ W,
    const float* __restrict__ bias, float* __restrict__ out, int split)
{
    __shared__ float Ast[16][64];   // [k][m] transposed
    __shared__ float Bst[16][64];   // [k][n] transposed

    const int tid  = threadIdx.x;
    const int tx   = tid & 15;
    const int ty   = tid >> 4;
    const int lrow = tid >> 2;          // 0..63
    const int lk   = (tid & 3) << 2;    // 0,4,8,12

    const float* Ap = X + (blockIdx.y * 64 + lrow) * DM + lk;
    const float* Bp = W + (blockIdx.x * 64 + lrow) * DM + lk;

    float acc[4][4] = {};

    for (int k0 = 0; k0 < DM; k0 += 16) {
        float4 a = *(const float4*)(Ap + k0);
        float4 b = *(const float4*)(Bp + k0);
        __syncthreads();
        Ast[lk+0][lrow] = a.x; Ast[lk+1][lrow] = a.y;
        Ast[lk+2][lrow] = a.z; Ast[lk+3][lrow] = a.w;
        Bst[lk+0][lrow] = b.x; Bst[lk+1][lrow] = b.y;
        Bst[lk+2][lrow] = b.z; Bst[lk+3][lrow] = b.w;
        __syncthreads();
        #pragma unroll
        for (int kk = 0; kk < 16; ++kk) {
            float4 av = *(const float4*)&Ast[kk][ty << 2];
            float4 bv = *(const float4*)&Bst[kk][tx << 2];
            acc[0][0] += av.x*bv.x; acc[0][1] += av.x*bv.y; acc[0][2] += av.x*bv.z; acc[0][3] += av.x*bv.w;
            acc[1][0] += av.y*bv.x; acc[1][1] += av.y*bv.y; acc[1][2] += av.y*bv.z; acc[1][3] += av.y*bv.w;
            acc[2][0] += av.z*bv.x; acc[2][1] += av.z*bv.y; acc[2][2] += av.z*bv.z; acc[2][3] += av.z*bv.w;
            acc[3][0] += av.w*bv.x; acc[3][1] += av.w*bv.y; acc[3][2] += av.w*bv.z; acc[3][3] += av.w*bv.w;
        }
    }

    const int m0 = blockIdx.y * 64 + (ty << 2);
    const int n0 = blockIdx.x * 64 + (tx << 2);
    #pragma unroll
    for (int r = 0; r < 4; ++r) {
        const int m = m0 + r;
        const int b = m >> 12;
        const int s = m & (SEQ - 1);
        #pragma unroll
        for (int c = 0; c < 4; ++c) {
            const int n = n0 + c;
            const float v = acc[r][c] + bias[n];
            if (split) {
                const int h = n >> 6, d = n & 63;
                out[(((b*NH + h) * SEQ) + s) * DK + d] = v;
            } else {
                out[m * DM + n] = v;
            }
        }
    }
}

// ---------------------------------------------------------------------------
// Flash attention, fp32. One block = 64 q-rows of one (b,h).
// smem: Qst[d][i], Kst[d][j], Vs[j][d] (stride 64), Ps[j][i] (stride 65).
// Online softmax, stats in registers, 16-lane shuffle reductions.
// ---------------------------------------------------------------------------
#define ATTN_SMEM ((3*64*64 + 64*65) * 4)   // 65792 bytes

__global__ __launch_bounds__(256) void attn_kernel(
    const float* __restrict__ q, const float* __restrict__ k,
    const float* __restrict__ v, float* __restrict__ o)
{
    extern __shared__ float sm[];
    float* Qst = sm;            // [64][64]  (d-major)
    float* Kst = sm + 4096;     // [64][64]  (d-major)
    float* Vs  = sm + 8192;     // [64][64]  (j-major)
    float* Ps  = sm + 12288;    // [64][65]  (j-major, scalar access)

    const int tid = threadIdx.x;
    const int tx  = tid & 15;
    const int ty  = tid >> 4;
    const int qb  = blockIdx.x;
    const int h   = blockIdx.y;
    const int b   = blockIdx.z;

    const float* Qg = q + ((size_t)(b*NH + h) * SEQ + qb * 64) * DK;
    const float* Kg = k + (size_t)(b*NH + h) * SEQ * DK;
    const float* Vg = v + (size_t)(b*NH + h) * SEQ * DK;

    const float SCALE = 0.125f;   // 1/sqrt(64)

    // Load Q tile transposed, pre-scaled. Tile = 4096 contiguous floats.
    #pragma unroll
    for (int u = 0; u < 4; ++u) {
        const int idx = tid + u * 256;        // 0..1023 (float4 units)
        const int row = idx >> 4;
        const int d0  = (idx & 15) << 2;
        float4 qv = *(const float4*)(Qg + idx * 4);
        Qst[(d0+0)*64 + row] = qv.x * SCALE;
        Qst[(d0+1)*64 + row] = qv.y * SCALE;
        Qst[(d0+2)*64 + row] = qv.z * SCALE;
        Qst[(d0+3)*64 + row] = qv.w * SCALE;
    }

    float mrow[4] = {-1e30f, -1e30f, -1e30f, -1e30f};
    float lsum[4] = {0.f, 0.f, 0.f, 0.f};
    float acc[4][4] = {};

    for (int kt = 0; kt < SEQ / 64; ++kt) {
        __syncthreads();   // prior iter done reading Kst/Vs (and orders Q tile on kt=0)
        const float* Kt = Kg + kt * 4096;
        const float* Vt = Vg + kt * 4096;
        #pragma unroll
        for (int u = 0; u < 4; ++u) {
            const int idx = tid + u * 256;
            const int row = idx >> 4;
            const int d0  = (idx & 15) << 2;
            float4 kv = *(const float4*)(Kt + idx * 4);
            Kst[(d0+0)*64 + row] = kv.x;
            Kst[(d0+1)*64 + row] = kv.y;
            Kst[(d0+2)*64 + row] = kv.z;
            Kst[(d0+3)*64 + row] = kv.w;
            float4 vv = *(const float4*)(Vt + idx * 4);
            *(float4*)&Vs[idx * 4] = vv;
        }
        __syncthreads();

        // S = (Q*scale) K^T : 64x64x64
        float sv[4][4] = {};
        #pragma unroll 8
        for (int d = 0; d < 64; ++d) {
            float4 qa = *(const float4*)&Qst[d*64 + (ty << 2)];
            float4 kb = *(const float4*)&Kst[d*64 + (tx << 2)];
            sv[0][0] += qa.x*kb.x; sv[0][1] += qa.x*kb.y; sv[0][2] += qa.x*kb.z; sv[0][3] += qa.x*kb.w;
            sv[1][0] += qa.y*kb.x; sv[1][1] += qa.y*kb.y; sv[1][2] += qa.y*kb.z; sv[1][3] += qa.y*kb.w;
            sv[2][0] += qa.z*kb.x; sv[2][1] += qa.z*kb.y; sv[2][2] += qa.z*kb.z; sv[2][3] += qa.z*kb.w;
            sv[3][0] += qa.w*kb.x; sv[3][1] += qa.w*kb.y; sv[3][2] += qa.w*kb.z; sv[3][3] += qa.w*kb.w;
        }

        // Online softmax per row (row i = ty*4+r spans the 16-lane tx group)
        #pragma unroll
        for (int r = 0; r < 4; ++r) {
            float rm = fmaxf(fmaxf(sv[r][0], sv[r][1]), fmaxf(sv[r][2], sv[r][3]));
            #pragma unroll
            for (int off = 8; off; off >>= 1)
                rm = fmaxf(rm, __shfl_xor_sync(0xffffffffu, rm, off));
            const float mnew = fmaxf(mrow[r], rm);
            const float cf   = __expf(mrow[r] - mnew);
            mrow[r] = mnew;
            float p[4], rs = 0.f;
            #pragma unroll
            for (int c = 0; c < 4; ++c) { p[c] = __expf(sv[r][c] - mnew); rs += p[c]; }
            #pragma unroll
            for (int off = 8; off; off >>= 1)
                rs += __shfl_xor_sync(0xffffffffu, rs, off);
            lsum[r] = lsum[r] * cf + rs;
            #pragma unroll
            for (int c = 0; c < 4; ++c) acc[r][c] *= cf;
            #pragma unroll
            for (int c = 0; c < 4; ++c)
                Ps[((tx << 2) + c) * 65 + (ty << 2) + r] = p[c];
        }
        __syncthreads();

        // O += P * V : 64x64x64
        #pragma unroll 8
        for (int j = 0; j < 64; ++j) {
            float4 vv = *(const float4*)&Vs[j*64 + (tx << 2)];
            const float p0 = Ps[j*65 + (ty << 2) + 0];
            const float p1 = Ps[j*65 + (ty << 2) + 1];
            const float p2 = Ps[j*65 + (ty << 2) + 2];
            const float p3 = Ps[j*65 + (ty << 2) + 3];
            acc[0][0] += p0*vv.x; acc[0][1] += p0*vv.y; acc[0][2] += p0*vv.z; acc[0][3] += p0*vv.w;
            acc[1][0] += p1*vv.x; acc[1][1] += p1*vv.y; acc[1][2] += p1*vv.z; acc[1][3] += p1*vv.w;
            acc[2][0] += p2*vv.x; acc[2][1] += p2*vv.y; acc[2][2] += p2*vv.z; acc[2][3] += p2*vv.w;
            acc[3][0] += p3*vv.x; acc[3][1] += p3*vv.y; acc[3][2] += p3*vv.z; acc[3][3] += p3*vv.w;
        }
    }

    // Epilogue: O /= l, write interleaved [b, s, h*64+d] for the output GEMM.
    #pragma unroll
    for (int r = 0; r < 4; ++r) {
        const float invl = 1.0f / lsum[r];
        const int srow = qb * 64 + (ty << 2) + r;
        float* orow = o + ((size_t)b * SEQ + srow) * DM + h * DK + (tx << 2);
        #pragma unroll
        for (int c = 0; c < 4; ++c)
            orow[c] = acc[r][c] * invl;
    }
}

// ---------------------------------------------------------------------------
extern "C" void kernel_launch(void* const* d_in, const int* in_sizes, int n_in,
                              void* d_out, int out_size)
{
    const float* query = (const float*)d_in[0];
    const float* key   = (const float*)d_in[1];
    const float* value = (const float*)d_in[2];
    const float* wq    = (const float*)d_in[3];
    const float* bq    = (const float*)d_in[4];
    const float* wk    = (const float*)d_in[5];
    const float* bk    = (const float*)d_in[6];
    const float* wv    = (const float*)d_in[7];
    const float* bv    = (const float*)d_in[8];
    const float* wo    = (const float*)d_in[9];
    const float* bo    = (const float*)d_in[10];

    float *qs, *ks, *vs, *os;
    cudaGetSymbolAddress((void**)&qs, g_q);
    cudaGetSymbolAddress((void**)&ks, g_k);
    cudaGetSymbolAddress((void**)&vs, g_v);
    cudaGetSymbolAddress((void**)&os, g_o);

    cudaFuncSetAttribute(attn_kernel,
                         cudaFuncAttributeMaxDynamicSharedMemorySize, ATTN_SMEM);

    dim3 pg(DM / 64, MTOT / 64);   // (12, 128)
    proj_nt<<<pg, 256>>>(query, wq, bq, qs, 1);
    proj_nt<<<pg, 256>>>(key,   wk, bk, ks, 1);
    proj_nt<<<pg, 256>>>(value, wv, bv, vs, 1);

    attn_kernel<<<dim3(SEQ / 64, NH, BATCH), 256, ATTN_SMEM>>>(qs, ks, vs, os);

    proj_nt<<<pg, 256>>>(os, wo, bo, (float*)d_out, 0);
}